// round 3
// baseline (speedup 1.0000x reference)
#include <cuda_runtime.h>

#define NB 4
#define PRE 512
#define NC 2048
#define TANCH 261120
#define NBIN 8192
#define CANDCAP 2048
#define NBLK 132

// ---------------- scratch (device globals; zero-initialized) --------------
__device__ int g_hist[16][NBIN];
__device__ int g_ccnt[16];
__device__ int g_sync;
__device__ unsigned long long g_cand[16][CANDCAP];
__device__ float g_box[NB][NC][5];
__device__ float g_score[NB][NC];
__device__ unsigned char g_valid[NB][NC];
__device__ unsigned long long g_key[NB][NC];
__device__ float g_sbox[NB][NC][5];
__device__ float g_sscore[NB][NC];
__device__ unsigned char g_svalid[NB][NC];
__device__ float g_geom[NB][NC][16];   // x0..y3, area, cx, cy, r, xmin,xmax,ymin,ymax
__device__ unsigned long long g_mask[NB][NC][32];

__device__ const int c_aoff[4] = {0, 196608, 245760, 258048};

__device__ __forceinline__ unsigned fflip(float f) {
    unsigned u = __float_as_uint(f);
    return (u & 0x80000000u) ? ~u : (u | 0x80000000u);
}
__device__ __forceinline__ float funflip(unsigned u) {
    return __uint_as_float((u & 0x80000000u) ? (u ^ 0x80000000u) : ~u);
}

// block mapping: 33 blocks per image
// lvl0: 24 x 8192, lvl1: 6 x 8192, lvl2: 2 x 6144, lvl3: 1 x 3072
__device__ __forceinline__ void map_block(int bx, int& b, int& lvl, int& c0, int& n) {
    b = bx / 33;
    int t = bx % 33;
    if (t < 24)      { lvl = 0; c0 = t * 8192;        n = 8192; }
    else if (t < 30) { lvl = 1; c0 = (t - 24) * 8192; n = 8192; }
    else if (t < 32) { lvl = 2; c0 = (t - 30) * 6144; n = 6144; }
    else             { lvl = 3; c0 = 0;               n = 3072; }
}

__device__ __forceinline__ void hist_add(int* h, unsigned bin) {
    unsigned m = __match_any_sync(0xffffffffu, bin);
    int leader = __ffs(m) - 1;
    if ((threadIdx.x & 31) == leader) atomicAdd(&h[bin], __popc(m));
}

// ------------- stage 1 (fused): hist -> grid barrier -> thresh -> collect --
__global__ __launch_bounds__(256) void select_kernel(const float* __restrict__ o0,
                                                     const float* __restrict__ o1,
                                                     const float* __restrict__ o2,
                                                     const float* __restrict__ o3) {
    __shared__ int h[NBIN];
    for (int i = threadIdx.x; i < NBIN; i += 256) h[i] = 0;
    __syncthreads();
    int b, lvl, c0, n;
    map_block(blockIdx.x, b, lvl, c0, n);
    const float* base = lvl == 0 ? o0 : lvl == 1 ? o1 : lvl == 2 ? o2 : o3;
    int H = 256 >> lvl, HW = H * H;
    int NL = 3 * HW;
    int seg = b * 4 + lvl;
    const float* p = base + (long long)b * NL + c0;
    const float4* p4 = (const float4*)p;
    int n4 = n >> 2;

    // ---- phase 1: local histogram (warp-aggregated shared atomics) ----
    for (int m = threadIdx.x; m < n4; m += 256) {
        float4 v = p4[m];
        hist_add(h, fflip(v.x) >> 19);
        hist_add(h, fflip(v.y) >> 19);
        hist_add(h, fflip(v.z) >> 19);
        hist_add(h, fflip(v.w) >> 19);
    }
    __syncthreads();
    for (int i = threadIdx.x; i < NBIN; i += 256)
        if (h[i]) atomicAdd(&g_hist[seg][i], h[i]);

    // ---- grid barrier (all 132 blocks co-resident: grid < #SMs) ----
    __syncthreads();
    if (threadIdx.x == 0) {
        __threadfence();
        atomicAdd(&g_sync, 1);
        while (atomicAdd(&g_sync, 0) < NBLK) {}
        __threadfence();
    }
    __syncthreads();

    // ---- phase 2: per-block threshold for own segment (L2 reads) ----
    __shared__ int part[256];
    __shared__ unsigned s_th;
    {
        int t = threadIdx.x;
        int s = 0;
#pragma unroll 4
        for (int k = 0; k < 32; k++)
            s += __ldcg(&g_hist[seg][NBIN - 1 - t * 32 - k]);
        part[t] = s;
    }
    __syncthreads();
    if (threadIdx.x == 0) {
        int cum = 0, th = 0;
        for (int c = 0; c < 256; c++) {
            if (cum + part[c] >= PRE) {
                int c2 = cum;
                for (int k = 0; k < 32; k++) {
                    int bin = NBIN - 1 - c * 32 - k;
                    c2 += __ldcg(&g_hist[seg][bin]);
                    if (c2 >= PRE) { th = bin; break; }
                }
                break;
            }
            cum += part[c];
        }
        s_th = (unsigned)th;
    }
    __syncthreads();
    unsigned th = s_th;

    // ---- phase 3: collect candidates (data now L2-hot) ----
    for (int m = threadIdx.x; m < n4; m += 256) {
        float4 v = p4[m];
        float vals[4] = {v.x, v.y, v.z, v.w};
#pragma unroll
        for (int s = 0; s < 4; s++) {
            unsigned u = fflip(vals[s]);
            if ((u >> 19) >= th) {
                int gm = c0 + m * 4 + s;
                int idx = (gm % HW) * 3 + gm / HW;   // (y*W+x)*A + a order
                int pos = atomicAdd(&g_ccnt[seg], 1);
                if (pos < CANDCAP)
                    g_cand[seg][pos] = (((unsigned long long)u) << 32) | (unsigned)(~idx);
            }
        }
    }
}

// ------- stage 2 (fused): per-segment sort -> exact top-512 -> decode ------
__global__ __launch_bounds__(1024) void sortdecode_kernel(const float* __restrict__ d0,
                                                          const float* __restrict__ d1,
                                                          const float* __restrict__ d2,
                                                          const float* __restrict__ d3,
                                                          const float* __restrict__ anchors) {
    int seg = blockIdx.x;
    int b = seg >> 2, lvl = seg & 3;
    __shared__ unsigned long long sk[CANDCAP];
    int cnt = g_ccnt[seg];
    if (cnt > CANDCAP) cnt = CANDCAP;
    int M = (cnt <= 1024) ? 1024 : CANDCAP;
    for (int i = threadIdx.x; i < M; i += 1024)
        sk[i] = (i < cnt) ? g_cand[seg][i] : 0ull;
    __syncthreads();

    // scratch re-zero for next replay (globals start zeroed at load)
    if (threadIdx.x == 0) {
        g_ccnt[seg] = 0;
        if (seg == 0) g_sync = 0;
    }
    for (int i = threadIdx.x; i < NBIN; i += 1024) g_hist[seg][i] = 0;

    for (int ksz = 2; ksz <= M; ksz <<= 1) {
        for (int j = ksz >> 1; j > 0; j >>= 1) {
            for (int i = threadIdx.x; i < M; i += 1024) {
                int l = i ^ j;
                if (l > i) {
                    unsigned long long a = sk[i], c = sk[l];
                    bool desc = ((i & ksz) == 0);
                    if (desc ? (a < c) : (a > c)) { sk[i] = c; sk[l] = a; }
                }
            }
            __syncthreads();
        }
    }

    // decode top-512 of this segment
    int t = threadIdx.x;
    if (t < PRE) {
        unsigned long long kk = sk[t];
        float val = funflip((unsigned)(kk >> 32));
        int li = (int)(~(unsigned)(kk & 0xFFFFFFFFull));
        int H = 256 >> lvl, HW = H * H;
        int a = li % 3, cell = li / 3;
        int x = cell % H, y = cell / H;
        const float* dl = lvl == 0 ? d0 : lvl == 1 ? d1 : lvl == 2 ? d2 : d3;
        long long bi = ((long long)b * 18 + a * 6) * HW + (long long)y * H + x;
        float dx = dl[bi], dy = dl[bi + HW], dw = dl[bi + 2LL * HW],
              dh = dl[bi + 3LL * HW], ds = dl[bi + 4LL * HW], dc = dl[bi + 5LL * HW];
        int ta = c_aoff[lvl] + li;
        const float* an = anchors + ((long long)b * TANCH + ta) * 5;
        float ax = an[0], ay = an[1], aw = an[2], ah = an[3], aa = an[4];
        const float LOGM = 4.135166556742356f;
        dw = fminf(dw, LOGM);
        dh = fminf(dh, LOGM);
        float bw = aw * expf(dw), bh = ah * expf(dh);
        float bcx = ax + dx * aw, bcy = ay + dy * ah;
        float ang = aa + atan2f(ds, dc);
        float sc = 0.5f + 0.5f * tanhf(0.5f * val);   // XLA logistic form
        bool vd = (bw >= 1e-3f) && (bh >= 1e-3f) && (sc >= 0.0f);
        int pos = lvl * PRE + t;
        g_box[b][pos][0] = bcx; g_box[b][pos][1] = bcy;
        g_box[b][pos][2] = bw;  g_box[b][pos][3] = bh;
        g_box[b][pos][4] = ang;
        g_score[b][pos] = sc;
        g_valid[b][pos] = vd ? 1 : 0;
        unsigned u = vd ? __float_as_uint(sc) : 0u;   // score desc, pos asc tiebreak
        g_key[b][pos] = (((unsigned long long)u) << 32) | (unsigned)(2047 - pos);
    }
}

// ---------------- stage 3: per-image sort + geometry -----------------------
__global__ __launch_bounds__(1024) void sort_geom_kernel() {
    int b = blockIdx.x;
    __shared__ unsigned long long sk[NC];
    for (int i = threadIdx.x; i < NC; i += 1024) sk[i] = g_key[b][i];
    __syncthreads();
    for (int ksz = 2; ksz <= NC; ksz <<= 1) {
        for (int j = ksz >> 1; j > 0; j >>= 1) {
            for (int i = threadIdx.x; i < NC; i += 1024) {
                int l = i ^ j;
                if (l > i) {
                    unsigned long long a = sk[i], c = sk[l];
                    bool desc = ((i & ksz) == 0);
                    if (desc ? (a < c) : (a > c)) { sk[i] = c; sk[l] = a; }
                }
            }
            __syncthreads();
        }
    }
    for (int i = threadIdx.x; i < NC; i += 1024) {
        int pos = 2047 - (int)(unsigned)(sk[i] & 0xFFFFFFFFull);
        int lvl = pos >> 9;
        float b0 = g_box[b][pos][0], b1 = g_box[b][pos][1];
        float w = g_box[b][pos][2], h = g_box[b][pos][3], ang = g_box[b][pos][4];
        g_sbox[b][i][0] = b0; g_sbox[b][i][1] = b1;
        g_sbox[b][i][2] = w;  g_sbox[b][i][3] = h;  g_sbox[b][i][4] = ang;
        unsigned char vd = g_valid[b][pos];
        g_svalid[b][i] = vd;
        g_sscore[b][i] = vd ? g_score[b][pos] : __int_as_float(0xff800000);
        float off = 8192.0f * (float)lvl;
        float cx = b0 + off, cy = b1 + off;
        float ca = cosf(ang), sa = sinf(ang);
        float hw = 0.5f * w, hh = 0.5f * h;
        float dxs[4] = {hw, -hw, -hw, hw};
        float dys[4] = {hh, hh, -hh, -hh};
        float xmn = 1e30f, xmx = -1e30f, ymn = 1e30f, ymx = -1e30f;
#pragma unroll
        for (int c = 0; c < 4; c++) {
            float xx = cx + dxs[c] * ca - dys[c] * sa;
            float yy = cy + dxs[c] * sa + dys[c] * ca;
            g_geom[b][i][2 * c] = xx;
            g_geom[b][i][2 * c + 1] = yy;
            xmn = fminf(xmn, xx); xmx = fmaxf(xmx, xx);
            ymn = fminf(ymn, yy); ymx = fmaxf(ymx, yy);
        }
        g_geom[b][i][8] = w * h;
        g_geom[b][i][9] = cx;
        g_geom[b][i][10] = cy;
        g_geom[b][i][11] = 0.5f * sqrtf(w * w + h * h);
        g_geom[b][i][12] = xmn;
        g_geom[b][i][13] = xmx;
        g_geom[b][i][14] = ymn;
        g_geom[b][i][15] = ymx;
    }
}

// ---------------- stage 4: rotated IoU suppression bitmask -----------------
__device__ float inter_area(float4 pA, float4 pB, float4 qA, float4 qB) {
    float px[8], py[8], ox[8], oy[8];
    px[0] = pA.x; py[0] = pA.y; px[1] = pA.z; py[1] = pA.w;
    px[2] = pB.x; py[2] = pB.y; px[3] = pB.z; py[3] = pB.w;
    float qx[4] = {qA.x, qA.z, qB.x, qB.z};
    float qy[4] = {qA.y, qA.w, qB.y, qB.w};
    int cnt = 4;
#pragma unroll
    for (int kk = 0; kk < 4; kk++) {
        float p1x = qx[kk], p1y = qy[kk];
        int k2 = (kk + 1) & 3;
        float ex = qx[k2] - p1x, ey = qy[k2] - p1y;
        int oc = 0;
        float d0 = ex * (py[0] - p1y) - ey * (px[0] - p1x);
        float dc = d0;
        for (int i = 0; i < cnt; i++) {
            int nx = (i + 1 < cnt) ? i + 1 : 0;
            float dn = (i + 1 < cnt) ? (ex * (py[i + 1] - p1y) - ey * (px[i + 1] - p1x)) : d0;
            bool ci = dc >= 0.f, ni = dn >= 0.f;
            if (ci) { ox[oc] = px[i]; oy[oc] = py[i]; oc++; }
            if (ci != ni) {
                float den = dc - dn;
                float tt = dc / ((den == 0.f) ? 1.f : den);
                ox[oc] = px[i] + tt * (px[nx] - px[i]);
                oy[oc] = py[i] + tt * (py[nx] - py[i]);
                oc++;
            }
            dc = dn;
        }
        cnt = oc;
        if (cnt == 0) break;
        for (int i = 0; i < cnt; i++) { px[i] = ox[i]; py[i] = oy[i]; }
    }
    if (cnt < 3) return 0.f;
    float s = 0.f;
    for (int i = 0; i < cnt; i++) {
        int nx = (i + 1 < cnt) ? i + 1 : 0;
        s += px[i] * py[nx] - px[nx] * py[i];
    }
    return 0.5f * fabsf(s);
}

__global__ __launch_bounds__(64) void mask_kernel() {
    int b = blockIdx.y;
    int tt = blockIdx.x;                       // triangular tile id -> (rb, cb)
    int rb = 0, rowrem = 32;
    while (tt >= rowrem) { tt -= rowrem; rowrem--; rb++; }
    int cb = rb + tt;

    int t = threadIdx.x;
    int row = rb * 64 + t;
    __shared__ float4 sg[64][4];
    const float4* gg = (const float4*)&g_geom[b][0][0];
    for (int i = t; i < 256; i += 64)
        ((float4*)sg)[i] = gg[cb * 256 + i];
    __syncthreads();

    float4 rA = gg[row * 4 + 0];
    float4 rB = gg[row * 4 + 1];
    float4 rC = gg[row * 4 + 2];   // area, cx, cy, r
    float4 rD = gg[row * 4 + 3];   // xmin, xmax, ymin, ymax
    unsigned long long bits = 0;
    int j0 = (cb == rb) ? t + 1 : 0;
    for (int j = j0; j < 64; j++) {
        float4 cC = sg[j][2];
        float ddx = rC.y - cC.y, ddy = rC.z - cC.z;
        float rr = rC.w + cC.w;
        if (ddx * ddx + ddy * ddy >= rr * rr) continue;     // disjoint
        float ai = rC.x, aj = cC.x;
        float S = ai + aj;
        float mn = fminf(ai, aj), mx = fmaxf(ai, aj);
        if (mn <= 0.7f * mx) continue;                      // IoU<=0.7 area bound
        float4 cD = sg[j][3];
        float xl = fmaxf(rD.x, cD.x), xr = fminf(rD.y, cD.y);
        float yl = fmaxf(rD.z, cD.z), yr = fminf(rD.w, cD.w);
        float ub = fmaxf(xr - xl, 0.f) * fmaxf(yr - yl, 0.f);
        if (ub * 1.7f < S * 0.6993f) continue;              // AABB bound (safety margin)
        float inter = inter_area(rA, rB, sg[j][0], sg[j][1]);
        float iou = inter / (S - inter + 1e-7f);
        if (iou > 0.7f) bits |= (1ull << j);
    }
    g_mask[b][row][cb] = bits;
}

// ---------- stage 5 (fused): greedy scan + padded output write ------------
// output layout: boxes [B,512,5] flattened, then scores [B,512]
__global__ __launch_bounds__(512) void greedy_out_kernel(float* __restrict__ out) {
    int b = blockIdx.x;
    int tid = threadIdx.x;
    __shared__ int keep[PRE];
    __shared__ int s_n;
    if (tid < 32) {
        int lane = tid;
        unsigned long long remv = 0;
        for (int j = 0; j < 64; j++)
            if (!g_svalid[b][lane * 64 + j]) remv |= (1ull << j);
        int n = 0;
        unsigned long long nextw = g_mask[b][0][lane];
        for (int i = 0; i < NC; i++) {
            unsigned long long cur = nextw;
            if (i + 1 < NC) nextw = g_mask[b][i + 1][lane];   // unconditional prefetch
            unsigned long long w = __shfl_sync(0xffffffffu, remv, (i >> 6));
            if (!((w >> (i & 63)) & 1ull)) {
                if (lane == 0) keep[n] = i;
                n++;
                remv |= cur;
                if (n >= PRE) break;
            }
        }
        if (lane == 0) s_n = n;
    }
    __syncthreads();
    int n = s_n;
    float v0 = 0, v1 = 0, v2 = 0, v3 = 0, v4 = 0, sc = 0;
    if (tid < n) {
        int i = keep[tid];
        v0 = g_sbox[b][i][0]; v1 = g_sbox[b][i][1];
        v2 = g_sbox[b][i][2]; v3 = g_sbox[b][i][3];
        v4 = g_sbox[b][i][4];
        sc = g_sscore[b][i];
    }
    float* ob = out + ((long long)b * PRE + tid) * 5;
    ob[0] = v0; ob[1] = v1; ob[2] = v2; ob[3] = v3; ob[4] = v4;
    out[NB * PRE * 5 + b * PRE + tid] = sc;
}

extern "C" void kernel_launch(void* const* d_in, const int* in_sizes, int n_in,
                              void* d_out, int out_size) {
    const float* obj[4] = {0, 0, 0, 0};
    const float* dlt[4] = {0, 0, 0, 0};
    const float* anch = 0;
    const int osz[4] = {786432, 196608, 49152, 12288};
    const int dsz[4] = {4718592, 1179648, 294912, 73728};
    for (int i = 0; i < n_in; i++) {
        int s = in_sizes[i];
        const float* p = (const float*)d_in[i];
        if (s == 5222400) { anch = p; continue; }
        for (int l = 0; l < 4; l++) {
            if (s == osz[l]) obj[l] = p;
            else if (s == dsz[l]) dlt[l] = p;
        }
    }
    select_kernel<<<NBLK, 256>>>(obj[0], obj[1], obj[2], obj[3]);
    sortdecode_kernel<<<16, 1024>>>(dlt[0], dlt[1], dlt[2], dlt[3], anch);
    sort_geom_kernel<<<NB, 1024>>>();
    mask_kernel<<<dim3(528, NB), 64>>>();
    greedy_out_kernel<<<NB, 512>>>((float*)d_out);
}